// round 13
// baseline (speedup 1.0000x reference)
#include <cuda_runtime.h>
#include <math.h>

#define F_BINS   2048
#define W_HALF   64
#define TAPS     (2*W_HALF)            // 128
#define NBUF_LEN (F_BINS + 2*W_HALF)   // 2176
#define NCH      48
#define NCT      96
#define NSLICE   4
#define HW_IN    (512*512)
#define BROWS    16
#define HROWS    (2*BROWS + 2)         // 34
#define USTEP    0.146484375f          // 300/2048

// scratch (static device globals -- no allocation)
__device__ __align__(16) unsigned int g_hist[NCT * NSLICE * F_BINS];  // 3.1 MB
__device__ __align__(16) float g_T[NCT * 257];
__device__ int g_done_bc;

#define KA_SMEM (F_BINS*4 + HROWS*256*4)   // 8192 + 34816 = 43008

// ---- kA: separable antialiased 2x downsample + private slice histogram ----
__global__ void __launch_bounds__(512, 3) kA_hist(const float* __restrict__ pred,
                                                  const float* __restrict__ tgt) {
    extern __shared__ unsigned char smraw[];
    unsigned int* sh_hist = reinterpret_cast<unsigned int*>(smraw);          // [2048]
    float* sh_h = reinterpret_cast<float*>(smraw + F_BINS*4);                // [34][256]

    const int ct    = blockIdx.x;   // 0..95
    const int slice = blockIdx.y;   // 0..3
    const int tid   = threadIdx.x;
    const int warp  = tid >> 5, lane = tid & 31;
    const unsigned FULL = 0xffffffffu;

    const int r0 = slice * 64;
    const int r1 = r0 + 64;

    const float* src = (ct < NCH) ? (pred + (size_t)ct * HW_IN)
                                  : (tgt  + (size_t)(ct - NCH) * HW_IN);

    for (int i = tid; i < F_BINS; i += 512) sh_hist[i] = 0u;
    __syncthreads();

    for (int oyb = r0; oyb < r1; oyb += BROWS) {
        for (int lr = warp; lr < HROWS; lr += 16) {
            int iy = 2*oyb - 1 + lr;
            iy = iy < 0 ? 0 : (iy > 511 ? 511 : iy);
            const float4* row4 = reinterpret_cast<const float4*>(src + (size_t)iy * 512);
            float4 v0 = row4[lane];
            float4 v1 = row4[32 + lane];
            float4 v2 = row4[64 + lane];
            float4 v3 = row4[96 + lane];
            float cl1 = __shfl_sync(FULL, v0.w, 31);
            float cl2 = __shfl_sync(FULL, v1.w, 31);
            float cl3 = __shfl_sync(FULL, v2.w, 31);
            float cr0 = __shfl_sync(FULL, v1.x, 0);
            float cr1 = __shfl_sync(FULL, v2.x, 0);
            float cr2 = __shfl_sync(FULL, v3.x, 0);
            float carryL[4] = {0.f, cl1, cl2, cl3};
            float carryR[4] = {cr0, cr1, cr2, 0.f};
            float4 vv[4] = {v0, v1, v2, v3};
            float2* hd = reinterpret_cast<float2*>(sh_h + lr*256);
            #pragma unroll
            for (int c = 0; c < 4; c++) {
                float4 v = vv[c];
                float left  = __shfl_up_sync(FULL, v.w, 1);
                if (lane == 0)  left  = carryL[c];
                float right = __shfl_down_sync(FULL, v.x, 1);
                if (lane == 31) right = carryR[c];
                float ha, hb;
                if (c == 0 && lane == 0)
                    ha = (3.f*v.x + 3.f*v.y + v.z) * (1.f/7.f);
                else
                    ha = (left + 3.f*v.x + 3.f*v.y + v.z) * 0.125f;
                if (c == 3 && lane == 31)
                    hb = (v.y + 3.f*v.z + 3.f*v.w) * (1.f/7.f);
                else
                    hb = (v.y + 3.f*v.z + 3.f*v.w + right) * 0.125f;
                hd[c*32 + lane] = make_float2(ha, hb);
            }
        }
        __syncthreads();

        for (int p = tid; p < BROWS*256; p += 512) {
            int oyl = p >> 8;
            int ox  = p & 255;
            int oy  = oyb + oyl;
            const float* hp = sh_h + (2*oyl)*256 + ox;
            float a0 = hp[0], a1 = hp[256], a2 = hp[512], a3 = hp[768];
            float inv = (oy == 0 || oy == 255) ? (1.f/7.f) : 0.125f;
            float w0 = (oy == 0)   ? 0.f : inv;
            float w3 = (oy == 255) ? 0.f : inv;
            float val = w0*a0 + 3.f*inv*(a1 + a2) + w3*a3;
            int bin = (int)(val * (float)F_BINS);
            bin = bin < 0 ? 0 : (bin > F_BINS-1 ? F_BINS-1 : bin);
            atomicAdd(&sh_hist[bin], 1u);
        }
        __syncthreads();
    }

    unsigned int* dst = g_hist + (size_t)(ct*NSLICE + slice) * F_BINS;
    const uint4* s4 = reinterpret_cast<const uint4*>(sh_hist);
    uint4* d4 = reinterpret_cast<uint4*>(dst);
    for (int i = tid; i < F_BINS/4; i += 512) d4[i] = s4[i];

    // PDL: this thread's writeback stores are program-order-before this trigger;
    // dependents see them after griddepcontrol.wait.
    asm volatile("griddepcontrol.launch_dependents;");
}

// ---- kBC: per-channel T(m) (direct store), then last CTA reduces to the scalar ----
__global__ void __launch_bounds__(512) kBC(float* __restrict__ out) {
    __shared__ __align__(16) float nbuf[NBUF_LEN];
    __shared__ float csuf[257];
    __shared__ float chunk[256];
    __shared__ int s_ticket;
    __shared__ float s_red[16];

    const int ct = blockIdx.x, tid = threadIdx.x;
    const int warp = tid >> 5, lane = tid & 31;
    const unsigned FULL = 0xffffffffu;
    const uint4* h4 = reinterpret_cast<const uint4*>(g_hist + (size_t)(NSLICE*ct) * F_BINS);

    // ---- prologue: independent of kA's data (overlaps kA tail under PDL) ----
    if (tid < W_HALF) {
        nbuf[tid] = 0.f;
        nbuf[W_HALF + F_BINS + tid] = 0.f;
    }
    float4 tr0;
    {
        float j0 = (float)(4*lane);
        tr0.x = 1.f / (1.f + expf(-USTEP * (j0 + 0.f - 63.5f)));
        tr0.y = 1.f / (1.f + expf(-USTEP * (j0 + 1.f - 63.5f)));
        tr0.z = 1.f / (1.f + expf(-USTEP * (j0 + 2.f - 63.5f)));
        tr0.w = 1.f / (1.f + expf(-USTEP * (j0 + 3.f - 63.5f)));
    }

    // ---- wait for kA's data ----
    asm volatile("griddepcontrol.wait;" ::: "memory");

    for (int k = tid; k < F_BINS/4; k += 512) {
        uint4 a = h4[k], b = h4[F_BINS/4 + k], c = h4[2*(F_BINS/4) + k], d = h4[3*(F_BINS/4) + k];
        float4 s;
        s.x = (float)(a.x + b.x + c.x + d.x);
        s.y = (float)(a.y + b.y + c.y + d.y);
        s.z = (float)(a.z + b.z + c.z + d.z);
        s.w = (float)(a.w + b.w + c.w + d.w);
        reinterpret_cast<float4*>(nbuf + W_HALF)[k] = s;
    }
    __syncthreads();

    // 8-bin chunk sums (one per coarse bin)
    if (tid < 256) {
        const float4* p4 = reinterpret_cast<const float4*>(nbuf + W_HALF) + tid*2;
        float4 v0 = p4[0], v1 = p4[1];
        chunk[tid] = (v0.x+v0.y+v0.z+v0.w) + (v1.x+v1.y+v1.z+v1.w);
    }
    __syncthreads();
    if (tid < 32) {      // suffix scan of 256 chunks
        float loc[8];
        float run = 0.f;
        #pragma unroll
        for (int i = 7; i >= 0; i--) { run += chunk[tid*8 + i]; loc[i] = run; }
        float t_l = run, suf = run;
        #pragma unroll
        for (int off = 1; off < 32; off <<= 1) {
            float v = __shfl_down_sync(FULL, suf, off);
            if (tid + off < 32) suf += v;
        }
        float above = suf - t_l;
        #pragma unroll
        for (int i = 0; i < 8; i++) csuf[tid*8 + i] = loc[i] + above;
        if (tid == 0) csuf[256] = 0.f;
    }
    __syncthreads();

    const float4* nb4 = reinterpret_cast<const float4*>(nbuf);
    float* gT = g_T + ct*257;
    int m = warp;
    for (; m + 16 <= 256; m += 32) {
        const float4* baseA = nb4 + m*2;          // window [8m-64, 8m+64) at padded offset 8m
        const float4* baseB = nb4 + (m+16)*2;
        float4 a0 = baseA[lane];
        float4 b0 = baseB[lane];
        float accA = a0.x*tr0.x + a0.y*tr0.y + a0.z*tr0.z + a0.w*tr0.w;
        float accB = b0.x*tr0.x + b0.y*tr0.y + b0.z*tr0.z + b0.w*tr0.w;
        #pragma unroll
        for (int off = 16; off; off >>= 1) {
            accA += __shfl_down_sync(FULL, accA, off);
            accB += __shfl_down_sync(FULL, accB, off);
        }
        if (lane == 0) {
            int ca = m + 8, cb = m + 24;
            gT[m]      = ((ca < 256) ? csuf[ca] : 0.f) + accA;
            gT[m + 16] = ((cb < 256) ? csuf[cb] : 0.f) + accB;
        }
    }
    if (m <= 256) {                                // warp 0 tail: m = 256
        const float4* base = nb4 + m*2;
        float4 a0 = base[lane];
        float acc = a0.x*tr0.x + a0.y*tr0.y + a0.z*tr0.z + a0.w*tr0.w;
        #pragma unroll
        for (int off = 16; off; off >>= 1)
            acc += __shfl_down_sync(FULL, acc, off);
        if (lane == 0) gT[m] = acc;                // suffix is 0 for m=256
    }

    // ---- ticket: last CTA reduces ----
    __syncthreads();
    if (tid == 0) {
        __threadfence();                 // release: this CTA's gT stores -> L2
        s_ticket = atomicAdd(&g_done_bc, 1);
        if (s_ticket == NCT - 1) {
            atomicExch(&g_done_bc, 0);   // self-reset for next replay
            __threadfence();             // acquire: other CTAs' gT stores
        }
    }
    __syncthreads();
    if (s_ticket != NCT - 1) return;

    float s = 0.f;
    for (int e = tid; e < NCH*256; e += 512) {
        int p  = e >> 8;
        int bb = e & 255;
        const float* Tp = g_T + p*257;
        const float* Tt = g_T + (NCH + p)*257;
        float p0 = __ldcg(&Tp[0]), t0 = __ldcg(&Tt[0]);
        float pe = __ldcg(&Tp[256]), te = __ldcg(&Tt[256]);
        float invp = 1.f / (p0 - pe);
        float invt = 1.f / (t0 - te);
        float cp  = (p0 - __ldcg(&Tp[bb+1])) * invp;
        float ctv = (t0 - __ldcg(&Tt[bb+1])) * invt;
        s += fabsf(cp - ctv);
    }
    #pragma unroll
    for (int off = 16; off; off >>= 1) s += __shfl_down_sync(FULL, s, off);
    if (lane == 0) s_red[warp] = s;
    __syncthreads();
    if (tid < 32) {
        float v = (tid < 16) ? s_red[tid] : 0.f;
        #pragma unroll
        for (int off = 16; off; off >>= 1) v += __shfl_down_sync(FULL, v, off);
        if (tid == 0) out[0] = v * (1.0f / (48.0f * 256.0f));
    }
}

extern "C" void kernel_launch(void* const* d_in, const int* in_sizes, int n_in,
                              void* d_out, int out_size) {
    const float* pred = (const float*)d_in[0];
    const float* tgt  = (const float*)d_in[1];
    float* out = (float*)d_out;

    cudaFuncSetAttribute(kA_hist, cudaFuncAttributeMaxDynamicSharedMemorySize, KA_SMEM);

    kA_hist<<<dim3(NCT, NSLICE), 512, KA_SMEM>>>(pred, tgt);

    // PDL launch: kBC may begin while kA drains; it synchronizes via griddepcontrol.wait.
    cudaLaunchAttribute attr[1];
    attr[0].id = cudaLaunchAttributeProgrammaticStreamSerialization;
    attr[0].val.programmaticStreamSerializationAllowed = 1;
    cudaLaunchConfig_t cfg = {};
    cfg.gridDim  = dim3(NCT, 1, 1);
    cfg.blockDim = dim3(512, 1, 1);
    cfg.dynamicSmemBytes = 0;
    cfg.stream = 0;
    cfg.attrs = attr;
    cfg.numAttrs = 1;
    cudaLaunchKernelEx(&cfg, kBC, out);
}

// round 14
// speedup vs baseline: 1.0772x; 1.0772x over previous
#include <cuda_runtime.h>
#include <math.h>

#define F_BINS   2048
#define W_HALF   64
#define TAPS     (2*W_HALF)            // 128
#define NBUF_LEN (F_BINS + 2*W_HALF)   // 2176
#define NCH      48
#define NCT      96
#define NSLICE   4
#define HW_IN    (512*512)
#define BROWS    16
#define HROWS    (2*BROWS + 2)         // 34
#define USTEP    0.146484375f          // 300/2048

// scratch (static device globals -- no allocation)
__device__ __align__(16) unsigned int g_hist[NCT * NSLICE * F_BINS];  // 3.1 MB
__device__ __align__(16) float g_T[NCT * 257];
__device__ int g_done_bc;

#define KA_SMEM (F_BINS*4 + HROWS*256*4)   // 8192 + 34816 = 43008

// ---- kA: separable antialiased 2x downsample + private slice histogram ----
__global__ void __launch_bounds__(512, 3) kA_hist(const float* __restrict__ pred,
                                                  const float* __restrict__ tgt) {
    extern __shared__ unsigned char smraw[];
    unsigned int* sh_hist = reinterpret_cast<unsigned int*>(smraw);          // [2048]
    float* sh_h = reinterpret_cast<float*>(smraw + F_BINS*4);                // [34][256]

    const int ct    = blockIdx.x;   // 0..95
    const int slice = blockIdx.y;   // 0..3
    const int tid   = threadIdx.x;
    const int warp  = tid >> 5, lane = tid & 31;
    const unsigned FULL = 0xffffffffu;

    const int r0 = slice * 64;
    const int r1 = r0 + 64;

    const float* src = (ct < NCH) ? (pred + (size_t)ct * HW_IN)
                                  : (tgt  + (size_t)(ct - NCH) * HW_IN);

    for (int i = tid; i < F_BINS; i += 512) sh_hist[i] = 0u;
    __syncthreads();

    for (int oyb = r0; oyb < r1; oyb += BROWS) {
        for (int lr = warp; lr < HROWS; lr += 16) {
            int iy = 2*oyb - 1 + lr;
            iy = iy < 0 ? 0 : (iy > 511 ? 511 : iy);
            const float4* row4 = reinterpret_cast<const float4*>(src + (size_t)iy * 512);
            float4 v0 = row4[lane];
            float4 v1 = row4[32 + lane];
            float4 v2 = row4[64 + lane];
            float4 v3 = row4[96 + lane];
            float cl1 = __shfl_sync(FULL, v0.w, 31);
            float cl2 = __shfl_sync(FULL, v1.w, 31);
            float cl3 = __shfl_sync(FULL, v2.w, 31);
            float cr0 = __shfl_sync(FULL, v1.x, 0);
            float cr1 = __shfl_sync(FULL, v2.x, 0);
            float cr2 = __shfl_sync(FULL, v3.x, 0);
            float carryL[4] = {0.f, cl1, cl2, cl3};
            float carryR[4] = {cr0, cr1, cr2, 0.f};
            float4 vv[4] = {v0, v1, v2, v3};
            float2* hd = reinterpret_cast<float2*>(sh_h + lr*256);
            #pragma unroll
            for (int c = 0; c < 4; c++) {
                float4 v = vv[c];
                float left  = __shfl_up_sync(FULL, v.w, 1);
                if (lane == 0)  left  = carryL[c];
                float right = __shfl_down_sync(FULL, v.x, 1);
                if (lane == 31) right = carryR[c];
                float ha, hb;
                if (c == 0 && lane == 0)
                    ha = (3.f*v.x + 3.f*v.y + v.z) * (1.f/7.f);
                else
                    ha = (left + 3.f*v.x + 3.f*v.y + v.z) * 0.125f;
                if (c == 3 && lane == 31)
                    hb = (v.y + 3.f*v.z + 3.f*v.w) * (1.f/7.f);
                else
                    hb = (v.y + 3.f*v.z + 3.f*v.w + right) * 0.125f;
                hd[c*32 + lane] = make_float2(ha, hb);
            }
        }
        __syncthreads();

        for (int p = tid; p < BROWS*256; p += 512) {
            int oyl = p >> 8;
            int ox  = p & 255;
            int oy  = oyb + oyl;
            const float* hp = sh_h + (2*oyl)*256 + ox;
            float a0 = hp[0], a1 = hp[256], a2 = hp[512], a3 = hp[768];
            float inv = (oy == 0 || oy == 255) ? (1.f/7.f) : 0.125f;
            float w0 = (oy == 0)   ? 0.f : inv;
            float w3 = (oy == 255) ? 0.f : inv;
            float val = w0*a0 + 3.f*inv*(a1 + a2) + w3*a3;
            int bin = (int)(val * (float)F_BINS);
            bin = bin < 0 ? 0 : (bin > F_BINS-1 ? F_BINS-1 : bin);
            atomicAdd(&sh_hist[bin], 1u);
        }
        __syncthreads();
    }

    unsigned int* dst = g_hist + (size_t)(ct*NSLICE + slice) * F_BINS;
    const uint4* s4 = reinterpret_cast<const uint4*>(sh_hist);
    uint4* d4 = reinterpret_cast<uint4*>(dst);
    for (int i = tid; i < F_BINS/4; i += 512) d4[i] = s4[i];

    asm volatile("griddepcontrol.launch_dependents;");
}

// ---- kBC: per-channel T(m) with 1024 threads, then last CTA reduces ----
__global__ void __launch_bounds__(1024) kBC(float* __restrict__ out) {
    __shared__ __align__(16) float nbuf[NBUF_LEN];
    __shared__ float csuf[257];
    __shared__ float chunk[256];
    __shared__ int s_ticket;
    __shared__ float s_red[32];

    const int ct = blockIdx.x, tid = threadIdx.x;
    const int warp = tid >> 5, lane = tid & 31;
    const unsigned FULL = 0xffffffffu;
    const uint4* h4 = reinterpret_cast<const uint4*>(g_hist + (size_t)(NSLICE*ct) * F_BINS);

    // ---- prologue (independent of kA data) ----
    if (tid < W_HALF) {
        nbuf[tid] = 0.f;
        nbuf[W_HALF + F_BINS + tid] = 0.f;
    }
    float4 tr0;
    {
        float j0 = (float)(4*lane);
        tr0.x = 1.f / (1.f + expf(-USTEP * (j0 + 0.f - 63.5f)));
        tr0.y = 1.f / (1.f + expf(-USTEP * (j0 + 1.f - 63.5f)));
        tr0.z = 1.f / (1.f + expf(-USTEP * (j0 + 2.f - 63.5f)));
        tr0.w = 1.f / (1.f + expf(-USTEP * (j0 + 3.f - 63.5f)));
    }

    asm volatile("griddepcontrol.wait;" ::: "memory");

    // sum 4 slice histograms: 512 uint4 across 1024 threads
    if (tid < F_BINS/4) {
        uint4 a = h4[tid], b = h4[F_BINS/4 + tid], c = h4[2*(F_BINS/4) + tid], d = h4[3*(F_BINS/4) + tid];
        float4 s;
        s.x = (float)(a.x + b.x + c.x + d.x);
        s.y = (float)(a.y + b.y + c.y + d.y);
        s.z = (float)(a.z + b.z + c.z + d.z);
        s.w = (float)(a.w + b.w + c.w + d.w);
        reinterpret_cast<float4*>(nbuf + W_HALF)[tid] = s;
    }
    __syncthreads();

    // 8-bin chunk sums (one per coarse bin)
    if (tid < 256) {
        const float4* p4 = reinterpret_cast<const float4*>(nbuf + W_HALF) + tid*2;
        float4 v0 = p4[0], v1 = p4[1];
        chunk[tid] = (v0.x+v0.y+v0.z+v0.w) + (v1.x+v1.y+v1.z+v1.w);
    }
    __syncthreads();
    if (tid < 32) {      // suffix scan of 256 chunks
        float loc[8];
        float run = 0.f;
        #pragma unroll
        for (int i = 7; i >= 0; i--) { run += chunk[tid*8 + i]; loc[i] = run; }
        float t_l = run, suf = run;
        #pragma unroll
        for (int off = 1; off < 32; off <<= 1) {
            float v = __shfl_down_sync(FULL, suf, off);
            if (tid + off < 32) suf += v;
        }
        float above = suf - t_l;
        #pragma unroll
        for (int i = 0; i < 8; i++) csuf[tid*8 + i] = loc[i] + above;
        if (tid == 0) csuf[256] = 0.f;
    }
    __syncthreads();

    const float4* nb4 = reinterpret_cast<const float4*>(nbuf);
    float* gT = g_T + ct*257;
    // 32 warps; warp w covers m = w + 64k and w + 32 + 64k, k = 0..3 (all m in [0,256))
    #pragma unroll
    for (int k = 0; k < 4; k++) {
        int mA = warp + 64*k;
        int mB = mA + 32;
        const float4* baseA = nb4 + mA*2;     // window [8m-64, 8m+64) at padded offset 8m
        const float4* baseB = nb4 + mB*2;
        float4 a0 = baseA[lane];
        float4 b0 = baseB[lane];
        float accA = a0.x*tr0.x + a0.y*tr0.y + a0.z*tr0.z + a0.w*tr0.w;
        float accB = b0.x*tr0.x + b0.y*tr0.y + b0.z*tr0.z + b0.w*tr0.w;
        #pragma unroll
        for (int off = 16; off; off >>= 1) {
            accA += __shfl_down_sync(FULL, accA, off);
            accB += __shfl_down_sync(FULL, accB, off);
        }
        if (lane == 0) {
            int ca = mA + 8, cb = mB + 8;
            gT[mA] = ((ca < 256) ? csuf[ca] : 0.f) + accA;
            gT[mB] = ((cb < 256) ? csuf[cb] : 0.f) + accB;
        }
    }
    if (warp == 0) {                           // tail: m = 256
        const float4* base = nb4 + 256*2;
        float4 a0 = base[lane];
        float acc = a0.x*tr0.x + a0.y*tr0.y + a0.z*tr0.z + a0.w*tr0.w;
        #pragma unroll
        for (int off = 16; off; off >>= 1)
            acc += __shfl_down_sync(FULL, acc, off);
        if (lane == 0) gT[256] = acc;          // suffix is 0 for m=256
    }

    // ---- ticket: last CTA reduces ----
    __syncthreads();
    if (tid == 0) {
        __threadfence();                 // release: this CTA's gT stores -> L2
        s_ticket = atomicAdd(&g_done_bc, 1);
        if (s_ticket == NCT - 1) {
            atomicExch(&g_done_bc, 0);   // self-reset for next replay
            __threadfence();             // acquire: other CTAs' gT stores
        }
    }
    __syncthreads();
    if (s_ticket != NCT - 1) return;

    float s = 0.f;
    for (int e = tid; e < NCH*256; e += 1024) {
        int p  = e >> 8;
        int bb = e & 255;
        const float* Tp = g_T + p*257;
        const float* Tt = g_T + (NCH + p)*257;
        float p0 = __ldcg(&Tp[0]), t0 = __ldcg(&Tt[0]);
        float pe = __ldcg(&Tp[256]), te = __ldcg(&Tt[256]);
        float invp = 1.f / (p0 - pe);
        float invt = 1.f / (t0 - te);
        float cp  = (p0 - __ldcg(&Tp[bb+1])) * invp;
        float ctv = (t0 - __ldcg(&Tt[bb+1])) * invt;
        s += fabsf(cp - ctv);
    }
    #pragma unroll
    for (int off = 16; off; off >>= 1) s += __shfl_down_sync(FULL, s, off);
    if (lane == 0) s_red[warp] = s;
    __syncthreads();
    if (tid < 32) {
        float v = s_red[tid];
        #pragma unroll
        for (int off = 16; off; off >>= 1) v += __shfl_down_sync(FULL, v, off);
        if (tid == 0) out[0] = v * (1.0f / (48.0f * 256.0f));
    }
}

extern "C" void kernel_launch(void* const* d_in, const int* in_sizes, int n_in,
                              void* d_out, int out_size) {
    const float* pred = (const float*)d_in[0];
    const float* tgt  = (const float*)d_in[1];
    float* out = (float*)d_out;

    cudaFuncSetAttribute(kA_hist, cudaFuncAttributeMaxDynamicSharedMemorySize, KA_SMEM);

    kA_hist<<<dim3(NCT, NSLICE), 512, KA_SMEM>>>(pred, tgt);

    cudaLaunchAttribute attr[1];
    attr[0].id = cudaLaunchAttributeProgrammaticStreamSerialization;
    attr[0].val.programmaticStreamSerializationAllowed = 1;
    cudaLaunchConfig_t cfg = {};
    cfg.gridDim  = dim3(NCT, 1, 1);
    cfg.blockDim = dim3(1024, 1, 1);
    cfg.dynamicSmemBytes = 0;
    cfg.stream = 0;
    cfg.attrs = attr;
    cfg.numAttrs = 1;
    cudaLaunchKernelEx(&cfg, kBC, out);
}

// round 15
// speedup vs baseline: 1.3926x; 1.2928x over previous
#include <cuda_runtime.h>
#include <math.h>

#define F_BINS   2048
#define W_HALF   64
#define TAPS     (2*W_HALF)            // 128
#define NBUF_LEN (F_BINS + 2*W_HALF)   // 2176
#define NCH      48
#define NCT      96
#define NSLICE   4
#define HW_IN    (512*512)
#define BROWS    16
#define HROWS    (2*BROWS + 2)         // 34
#define USTEP    0.146484375f          // 300/2048

// scratch (static device global -- no allocation)
__device__ __align__(16) unsigned int g_hist[NCT * NSLICE * F_BINS];  // 3.1 MB

#define KA_SMEM (F_BINS*4 + HROWS*256*4)   // 8192 + 34816 = 43008

// ---- kA: separable antialiased 2x downsample + private slice histogram ----
__global__ void __launch_bounds__(512, 3) kA_hist(const float* __restrict__ pred,
                                                  const float* __restrict__ tgt,
                                                  float* __restrict__ out) {
    extern __shared__ unsigned char smraw[];
    unsigned int* sh_hist = reinterpret_cast<unsigned int*>(smraw);          // [2048]
    float* sh_h = reinterpret_cast<float*>(smraw + F_BINS*4);                // [34][256]

    const int ct    = blockIdx.x;   // 0..95
    const int slice = blockIdx.y;   // 0..3
    const int tid   = threadIdx.x;
    const int warp  = tid >> 5, lane = tid & 31;
    const unsigned FULL = 0xffffffffu;

    // zero the output accumulator (visible to kBC via PDL wait)
    if (ct == 0 && slice == 0 && tid == 0) out[0] = 0.f;

    const int r0 = slice * 64;
    const int r1 = r0 + 64;

    const float* src = (ct < NCH) ? (pred + (size_t)ct * HW_IN)
                                  : (tgt  + (size_t)(ct - NCH) * HW_IN);

    for (int i = tid; i < F_BINS; i += 512) sh_hist[i] = 0u;
    __syncthreads();

    for (int oyb = r0; oyb < r1; oyb += BROWS) {
        for (int lr = warp; lr < HROWS; lr += 16) {
            int iy = 2*oyb - 1 + lr;
            iy = iy < 0 ? 0 : (iy > 511 ? 511 : iy);
            const float4* row4 = reinterpret_cast<const float4*>(src + (size_t)iy * 512);
            float4 v0 = row4[lane];
            float4 v1 = row4[32 + lane];
            float4 v2 = row4[64 + lane];
            float4 v3 = row4[96 + lane];
            float cl1 = __shfl_sync(FULL, v0.w, 31);
            float cl2 = __shfl_sync(FULL, v1.w, 31);
            float cl3 = __shfl_sync(FULL, v2.w, 31);
            float cr0 = __shfl_sync(FULL, v1.x, 0);
            float cr1 = __shfl_sync(FULL, v2.x, 0);
            float cr2 = __shfl_sync(FULL, v3.x, 0);
            float carryL[4] = {0.f, cl1, cl2, cl3};
            float carryR[4] = {cr0, cr1, cr2, 0.f};
            float4 vv[4] = {v0, v1, v2, v3};
            float2* hd = reinterpret_cast<float2*>(sh_h + lr*256);
            #pragma unroll
            for (int c = 0; c < 4; c++) {
                float4 v = vv[c];
                float left  = __shfl_up_sync(FULL, v.w, 1);
                if (lane == 0)  left  = carryL[c];
                float right = __shfl_down_sync(FULL, v.x, 1);
                if (lane == 31) right = carryR[c];
                float ha, hb;
                if (c == 0 && lane == 0)
                    ha = (3.f*v.x + 3.f*v.y + v.z) * (1.f/7.f);
                else
                    ha = (left + 3.f*v.x + 3.f*v.y + v.z) * 0.125f;
                if (c == 3 && lane == 31)
                    hb = (v.y + 3.f*v.z + 3.f*v.w) * (1.f/7.f);
                else
                    hb = (v.y + 3.f*v.z + 3.f*v.w + right) * 0.125f;
                hd[c*32 + lane] = make_float2(ha, hb);
            }
        }
        __syncthreads();

        for (int p = tid; p < BROWS*256; p += 512) {
            int oyl = p >> 8;
            int ox  = p & 255;
            int oy  = oyb + oyl;
            const float* hp = sh_h + (2*oyl)*256 + ox;
            float a0 = hp[0], a1 = hp[256], a2 = hp[512], a3 = hp[768];
            float inv = (oy == 0 || oy == 255) ? (1.f/7.f) : 0.125f;
            float w0 = (oy == 0)   ? 0.f : inv;
            float w3 = (oy == 255) ? 0.f : inv;
            float val = w0*a0 + 3.f*inv*(a1 + a2) + w3*a3;
            int bin = (int)(val * (float)F_BINS);
            bin = bin < 0 ? 0 : (bin > F_BINS-1 ? F_BINS-1 : bin);
            atomicAdd(&sh_hist[bin], 1u);
        }
        __syncthreads();
    }

    unsigned int* dst = g_hist + (size_t)(ct*NSLICE + slice) * F_BINS;
    const uint4* s4 = reinterpret_cast<const uint4*>(sh_hist);
    uint4* d4 = reinterpret_cast<uint4*>(dst);
    for (int i = tid; i < F_BINS/4; i += 512) d4[i] = s4[i];

    asm volatile("griddepcontrol.launch_dependents;");
}

// ---- kBC: CTA p handles pred channel p AND target channel 48+p; loss is CTA-local ----
__global__ void __launch_bounds__(1024) kBC(float* __restrict__ out) {
    __shared__ __align__(16) float nbuf[2][NBUF_LEN];   // [pred|tgt] padded fine hist
    __shared__ float chunk[2][256];
    __shared__ float csuf[2][257];
    __shared__ float Tsm[2][257];
    __shared__ float s_red[8];

    const int ct = blockIdx.x;      // 0..47 (channel pair)
    const int tid = threadIdx.x;
    const int warp = tid >> 5, lane = tid & 31;
    const unsigned FULL = 0xffffffffu;

    // ---- prologue (independent of kA data) ----
    if (tid < 256) {
        int c = (tid >> 7) & 1, half = (tid >> 6) & 1, i = tid & 63;
        nbuf[c][half ? (W_HALF + F_BINS + i) : i] = 0.f;
    }
    float4 tr0;
    {
        float j0 = (float)(4*lane);
        tr0.x = 1.f / (1.f + expf(-USTEP * (j0 + 0.f - 63.5f)));
        tr0.y = 1.f / (1.f + expf(-USTEP * (j0 + 1.f - 63.5f)));
        tr0.z = 1.f / (1.f + expf(-USTEP * (j0 + 2.f - 63.5f)));
        tr0.w = 1.f / (1.f + expf(-USTEP * (j0 + 3.f - 63.5f)));
    }

    asm volatile("griddepcontrol.wait;" ::: "memory");

    // ---- sum 4 slice histograms for both channels: one uint4 per thread ----
    {
        int c   = tid >> 9;           // 0 = pred(ct), 1 = tgt(48+ct)
        int idx = tid & 511;
        int ch  = (c == 0) ? ct : (NCH + ct);
        const uint4* h4 = reinterpret_cast<const uint4*>(g_hist) + (size_t)ch * NSLICE * (F_BINS/4);
        uint4 a = h4[idx], b = h4[512 + idx], cc = h4[1024 + idx], d = h4[1536 + idx];
        float4 s;
        s.x = (float)(a.x + b.x + cc.x + d.x);
        s.y = (float)(a.y + b.y + cc.y + d.y);
        s.z = (float)(a.z + b.z + cc.z + d.z);
        s.w = (float)(a.w + b.w + cc.w + d.w);
        reinterpret_cast<float4*>(&nbuf[c][W_HALF])[idx] = s;
    }
    __syncthreads();

    // ---- 8-bin chunk sums, both channels ----
    if (tid < 512) {
        int c = tid >> 8, i = tid & 255;
        const float4* p4 = reinterpret_cast<const float4*>(&nbuf[c][W_HALF]) + i*2;
        float4 v0 = p4[0], v1 = p4[1];
        chunk[c][i] = (v0.x+v0.y+v0.z+v0.w) + (v1.x+v1.y+v1.z+v1.w);
    }
    __syncthreads();

    // ---- suffix scans: warp 0 -> pred, warp 1 -> tgt ----
    if (warp < 2) {
        float loc[8];
        float run = 0.f;
        #pragma unroll
        for (int i = 7; i >= 0; i--) { run += chunk[warp][lane*8 + i]; loc[i] = run; }
        float t_l = run, suf = run;
        #pragma unroll
        for (int off = 1; off < 32; off <<= 1) {
            float v = __shfl_down_sync(FULL, suf, off);
            if (lane + off < 32) suf += v;
        }
        float above = suf - t_l;
        #pragma unroll
        for (int i = 0; i < 8; i++) csuf[warp][lane*8 + i] = loc[i] + above;
        if (lane == 0) csuf[warp][256] = 0.f;
    }
    __syncthreads();

    // ---- windowed sigmoid dot: warps 0-15 pred, 16-31 tgt ----
    {
        int c  = warp >> 4;
        int wl = warp & 15;
        const float4* nb4 = reinterpret_cast<const float4*>(nbuf[c]);
        #pragma unroll
        for (int k = 0; k < 8; k++) {
            int mA = wl + 32*k;
            int mB = mA + 16;
            const float4* baseA = nb4 + mA*2;    // window [8m-64,8m+64) at padded offset 8m
            const float4* baseB = nb4 + mB*2;
            float4 a0 = baseA[lane];
            float4 b0 = baseB[lane];
            float accA = a0.x*tr0.x + a0.y*tr0.y + a0.z*tr0.z + a0.w*tr0.w;
            float accB = b0.x*tr0.x + b0.y*tr0.y + b0.z*tr0.z + b0.w*tr0.w;
            #pragma unroll
            for (int off = 16; off; off >>= 1) {
                accA += __shfl_down_sync(FULL, accA, off);
                accB += __shfl_down_sync(FULL, accB, off);
            }
            if (lane == 0) {
                int ca = mA + 8, cb = mB + 8;
                Tsm[c][mA] = ((ca < 256) ? csuf[c][ca] : 0.f) + accA;
                Tsm[c][mB] = ((cb < 256) ? csuf[c][cb] : 0.f) + accB;
            }
        }
        if (wl == 0) {                            // tail m = 256 (warps 0 and 16)
            const float4* base = nb4 + 256*2;
            float4 a0 = base[lane];
            float acc = a0.x*tr0.x + a0.y*tr0.y + a0.z*tr0.z + a0.w*tr0.w;
            #pragma unroll
            for (int off = 16; off; off >>= 1)
                acc += __shfl_down_sync(FULL, acc, off);
            if (lane == 0) Tsm[c][256] = acc;
        }
    }
    __syncthreads();

    // ---- CTA-local loss over 256 bins ----
    if (warp < 8) {
        float s = 0.f;
        if (tid < 256) {
            float p0 = Tsm[0][0], pe = Tsm[0][256];
            float t0 = Tsm[1][0], te = Tsm[1][256];
            float cp  = (p0 - Tsm[0][tid+1]) / (p0 - pe);
            float ctv = (t0 - Tsm[1][tid+1]) / (t0 - te);
            s = fabsf(cp - ctv);
        }
        #pragma unroll
        for (int off = 16; off; off >>= 1)
            s += __shfl_down_sync(FULL, s, off);
        if (lane == 0) s_red[warp] = s;
    }
    __syncthreads();
    if (warp == 0) {
        float v = (lane < 8) ? s_red[lane] : 0.f;
        #pragma unroll
        for (int off = 4; off; off >>= 1)
            v += __shfl_down_sync(FULL, v, off);
        if (lane == 0) atomicAdd(out, v * (1.0f / (48.0f * 256.0f)));
    }
}

extern "C" void kernel_launch(void* const* d_in, const int* in_sizes, int n_in,
                              void* d_out, int out_size) {
    const float* pred = (const float*)d_in[0];
    const float* tgt  = (const float*)d_in[1];
    float* out = (float*)d_out;

    cudaFuncSetAttribute(kA_hist, cudaFuncAttributeMaxDynamicSharedMemorySize, KA_SMEM);

    kA_hist<<<dim3(NCT, NSLICE), 512, KA_SMEM>>>(pred, tgt, out);

    cudaLaunchAttribute attr[1];
    attr[0].id = cudaLaunchAttributeProgrammaticStreamSerialization;
    attr[0].val.programmaticStreamSerializationAllowed = 1;
    cudaLaunchConfig_t cfg = {};
    cfg.gridDim  = dim3(NCH, 1, 1);
    cfg.blockDim = dim3(1024, 1, 1);
    cfg.dynamicSmemBytes = 0;
    cfg.stream = 0;
    cfg.attrs = attr;
    cfg.numAttrs = 1;
    cudaLaunchKernelEx(&cfg, kBC, out);
}

// round 16
// speedup vs baseline: 1.4314x; 1.0279x over previous
#include <cuda_runtime.h>
#include <math.h>

#define F_BINS   2048
#define W_HALF   64
#define TAPS     (2*W_HALF)            // 128
#define NBUF_LEN (F_BINS + 2*W_HALF)   // 2176
#define NCH      48
#define NCT      96
#define NSLICE   4
#define HW_IN    (512*512)
#define BROWS    16
#define HROWS    (2*BROWS + 2)         // 34
#define USTEP    0.146484375f          // 300/2048

// scratch (static device global -- no allocation)
__device__ __align__(16) unsigned int g_hist[NCT * NSLICE * F_BINS];  // 3.1 MB

#define KA_SMEM (F_BINS*4 + HROWS*256*4)   // 8192 + 34816 = 43008

// ---- kA: separable antialiased 2x downsample + private slice histogram ----
__global__ void __launch_bounds__(512, 3) kA_hist(const float* __restrict__ pred,
                                                  const float* __restrict__ tgt,
                                                  float* __restrict__ out) {
    extern __shared__ unsigned char smraw[];
    unsigned int* sh_hist = reinterpret_cast<unsigned int*>(smraw);          // [2048]
    float* sh_h = reinterpret_cast<float*>(smraw + F_BINS*4);                // [34][256]

    const int ct    = blockIdx.x;   // 0..95
    const int slice = blockIdx.y;   // 0..3
    const int tid   = threadIdx.x;
    const int warp  = tid >> 5, lane = tid & 31;
    const unsigned FULL = 0xffffffffu;

    // zero the output accumulator (visible to kBC via PDL wait)
    if (ct == 0 && slice == 0 && tid == 0) out[0] = 0.f;

    const int r0 = slice * 64;
    const int r1 = r0 + 64;

    const float* src = (ct < NCH) ? (pred + (size_t)ct * HW_IN)
                                  : (tgt  + (size_t)(ct - NCH) * HW_IN);

    for (int i = tid; i < F_BINS; i += 512) sh_hist[i] = 0u;
    __syncthreads();

    for (int oyb = r0; oyb < r1; oyb += BROWS) {
        // ---- stage HROWS horizontally-filtered input rows ----
        for (int lr = warp; lr < HROWS; lr += 16) {
            int iy = 2*oyb - 1 + lr;
            iy = iy < 0 ? 0 : (iy > 511 ? 511 : iy);
            const float4* row4 = reinterpret_cast<const float4*>(src + (size_t)iy * 512);
            float4 v0 = row4[lane];
            float4 v1 = row4[32 + lane];
            float4 v2 = row4[64 + lane];
            float4 v3 = row4[96 + lane];
            float cl1 = __shfl_sync(FULL, v0.w, 31);
            float cl2 = __shfl_sync(FULL, v1.w, 31);
            float cl3 = __shfl_sync(FULL, v2.w, 31);
            float cr0 = __shfl_sync(FULL, v1.x, 0);
            float cr1 = __shfl_sync(FULL, v2.x, 0);
            float cr2 = __shfl_sync(FULL, v3.x, 0);
            float carryL[4] = {0.f, cl1, cl2, cl3};
            float carryR[4] = {cr0, cr1, cr2, 0.f};
            float4 vv[4] = {v0, v1, v2, v3};
            float2* hd = reinterpret_cast<float2*>(sh_h + lr*256);
            #pragma unroll
            for (int c = 0; c < 4; c++) {
                float4 v = vv[c];
                float left  = __shfl_up_sync(FULL, v.w, 1);
                if (lane == 0)  left  = carryL[c];
                float right = __shfl_down_sync(FULL, v.x, 1);
                if (lane == 31) right = carryR[c];
                float ha, hb;
                if (c == 0 && lane == 0)
                    ha = (3.f*v.x + 3.f*v.y + v.z) * (1.f/7.f);
                else
                    ha = (left + 3.f*v.x + 3.f*v.y + v.z) * 0.125f;
                if (c == 3 && lane == 31)
                    hb = (v.y + 3.f*v.z + 3.f*v.w) * (1.f/7.f);
                else
                    hb = (v.y + 3.f*v.z + 3.f*v.w + right) * 0.125f;
                hd[c*32 + lane] = make_float2(ha, hb);
            }
        }
        __syncthreads();

        // ---- vertical combine: 4 consecutive output rows per thread (10 LDS / 4 px) ----
        {
            const int ox = tid & 255;
            #pragma unroll
            for (int g = tid >> 8; g < 4; g += 2) {
                float h[10];
                const float* col = sh_h + 8*g*256 + ox;
                #pragma unroll
                for (int i = 0; i < 10; i++) h[i] = col[i*256];
                #pragma unroll
                for (int j = 0; j < 4; j++) {
                    int oy = oyb + 4*g + j;
                    float inv = (oy == 0 || oy == 255) ? (1.f/7.f) : 0.125f;
                    float w0 = (oy == 0)   ? 0.f : inv;
                    float w3 = (oy == 255) ? 0.f : inv;
                    float val = w0*h[2*j] + 3.f*inv*(h[2*j+1] + h[2*j+2]) + w3*h[2*j+3];
                    int bin = (int)(val * (float)F_BINS);
                    bin = bin < 0 ? 0 : (bin > F_BINS-1 ? F_BINS-1 : bin);
                    atomicAdd(&sh_hist[bin], 1u);
                }
            }
        }
        __syncthreads();
    }

    unsigned int* dst = g_hist + (size_t)(ct*NSLICE + slice) * F_BINS;
    const uint4* s4 = reinterpret_cast<const uint4*>(sh_hist);
    uint4* d4 = reinterpret_cast<uint4*>(dst);
    for (int i = tid; i < F_BINS/4; i += 512) d4[i] = s4[i];

    asm volatile("griddepcontrol.launch_dependents;");
}

// ---- kBC: CTA p handles pred channel p AND target channel 48+p; loss is CTA-local ----
__global__ void __launch_bounds__(1024) kBC(float* __restrict__ out) {
    __shared__ __align__(16) float nbuf[2][NBUF_LEN];   // [pred|tgt] padded fine hist
    __shared__ float chunk[2][256];
    __shared__ float csuf[2][257];
    __shared__ float Tsm[2][257];
    __shared__ float s_red[8];

    const int ct = blockIdx.x;      // 0..47 (channel pair)
    const int tid = threadIdx.x;
    const int warp = tid >> 5, lane = tid & 31;
    const unsigned FULL = 0xffffffffu;

    // ---- prologue (independent of kA data) ----
    if (tid < 256) {
        int c = (tid >> 7) & 1, half = (tid >> 6) & 1, i = tid & 63;
        nbuf[c][half ? (W_HALF + F_BINS + i) : i] = 0.f;
    }
    float4 tr0;
    {
        float j0 = (float)(4*lane);
        tr0.x = 1.f / (1.f + expf(-USTEP * (j0 + 0.f - 63.5f)));
        tr0.y = 1.f / (1.f + expf(-USTEP * (j0 + 1.f - 63.5f)));
        tr0.z = 1.f / (1.f + expf(-USTEP * (j0 + 2.f - 63.5f)));
        tr0.w = 1.f / (1.f + expf(-USTEP * (j0 + 3.f - 63.5f)));
    }

    asm volatile("griddepcontrol.wait;" ::: "memory");

    // ---- sum 4 slice histograms for both channels: one uint4 per thread ----
    {
        int c   = tid >> 9;           // 0 = pred(ct), 1 = tgt(48+ct)
        int idx = tid & 511;
        int ch  = (c == 0) ? ct : (NCH + ct);
        const uint4* h4 = reinterpret_cast<const uint4*>(g_hist) + (size_t)ch * NSLICE * (F_BINS/4);
        uint4 a = h4[idx], b = h4[512 + idx], cc = h4[1024 + idx], d = h4[1536 + idx];
        float4 s;
        s.x = (float)(a.x + b.x + cc.x + d.x);
        s.y = (float)(a.y + b.y + cc.y + d.y);
        s.z = (float)(a.z + b.z + cc.z + d.z);
        s.w = (float)(a.w + b.w + cc.w + d.w);
        reinterpret_cast<float4*>(&nbuf[c][W_HALF])[idx] = s;
    }
    __syncthreads();

    // ---- 8-bin chunk sums, both channels ----
    if (tid < 512) {
        int c = tid >> 8, i = tid & 255;
        const float4* p4 = reinterpret_cast<const float4*>(&nbuf[c][W_HALF]) + i*2;
        float4 v0 = p4[0], v1 = p4[1];
        chunk[c][i] = (v0.x+v0.y+v0.z+v0.w) + (v1.x+v1.y+v1.z+v1.w);
    }
    __syncthreads();

    // ---- suffix scans: warp 0 -> pred, warp 1 -> tgt ----
    if (warp < 2) {
        float loc[8];
        float run = 0.f;
        #pragma unroll
        for (int i = 7; i >= 0; i--) { run += chunk[warp][lane*8 + i]; loc[i] = run; }
        float t_l = run, suf = run;
        #pragma unroll
        for (int off = 1; off < 32; off <<= 1) {
            float v = __shfl_down_sync(FULL, suf, off);
            if (lane + off < 32) suf += v;
        }
        float above = suf - t_l;
        #pragma unroll
        for (int i = 0; i < 8; i++) csuf[warp][lane*8 + i] = loc[i] + above;
        if (lane == 0) csuf[warp][256] = 0.f;
    }
    __syncthreads();

    // ---- windowed sigmoid dot: warps 0-15 pred, 16-31 tgt ----
    {
        int c  = warp >> 4;
        int wl = warp & 15;
        const float4* nb4 = reinterpret_cast<const float4*>(nbuf[c]);
        #pragma unroll
        for (int k = 0; k < 8; k++) {
            int mA = wl + 32*k;
            int mB = mA + 16;
            const float4* baseA = nb4 + mA*2;    // window [8m-64,8m+64) at padded offset 8m
            const float4* baseB = nb4 + mB*2;
            float4 a0 = baseA[lane];
            float4 b0 = baseB[lane];
            float accA = a0.x*tr0.x + a0.y*tr0.y + a0.z*tr0.z + a0.w*tr0.w;
            float accB = b0.x*tr0.x + b0.y*tr0.y + b0.z*tr0.z + b0.w*tr0.w;
            #pragma unroll
            for (int off = 16; off; off >>= 1) {
                accA += __shfl_down_sync(FULL, accA, off);
                accB += __shfl_down_sync(FULL, accB, off);
            }
            if (lane == 0) {
                int ca = mA + 8, cb = mB + 8;
                Tsm[c][mA] = ((ca < 256) ? csuf[c][ca] : 0.f) + accA;
                Tsm[c][mB] = ((cb < 256) ? csuf[c][cb] : 0.f) + accB;
            }
        }
        if (wl == 0) {                            // tail m = 256 (warps 0 and 16)
            const float4* base = nb4 + 256*2;
            float4 a0 = base[lane];
            float acc = a0.x*tr0.x + a0.y*tr0.y + a0.z*tr0.z + a0.w*tr0.w;
            #pragma unroll
            for (int off = 16; off; off >>= 1)
                acc += __shfl_down_sync(FULL, acc, off);
            if (lane == 0) Tsm[c][256] = acc;
        }
    }
    __syncthreads();

    // ---- CTA-local loss over 256 bins ----
    if (warp < 8) {
        float s = 0.f;
        if (tid < 256) {
            float p0 = Tsm[0][0], pe = Tsm[0][256];
            float t0 = Tsm[1][0], te = Tsm[1][256];
            float cp  = (p0 - Tsm[0][tid+1]) / (p0 - pe);
            float ctv = (t0 - Tsm[1][tid+1]) / (t0 - te);
            s = fabsf(cp - ctv);
        }
        #pragma unroll
        for (int off = 16; off; off >>= 1)
            s += __shfl_down_sync(FULL, s, off);
        if (lane == 0) s_red[warp] = s;
    }
    __syncthreads();
    if (warp == 0) {
        float v = (lane < 8) ? s_red[lane] : 0.f;
        #pragma unroll
        for (int off = 4; off; off >>= 1)
            v += __shfl_down_sync(FULL, v, off);
        if (lane == 0) atomicAdd(out, v * (1.0f / (48.0f * 256.0f)));
    }
}

extern "C" void kernel_launch(void* const* d_in, const int* in_sizes, int n_in,
                              void* d_out, int out_size) {
    const float* pred = (const float*)d_in[0];
    const float* tgt  = (const float*)d_in[1];
    float* out = (float*)d_out;

    cudaFuncSetAttribute(kA_hist, cudaFuncAttributeMaxDynamicSharedMemorySize, KA_SMEM);

    kA_hist<<<dim3(NCT, NSLICE), 512, KA_SMEM>>>(pred, tgt, out);

    cudaLaunchAttribute attr[1];
    attr[0].id = cudaLaunchAttributeProgrammaticStreamSerialization;
    attr[0].val.programmaticStreamSerializationAllowed = 1;
    cudaLaunchConfig_t cfg = {};
    cfg.gridDim  = dim3(NCH, 1, 1);
    cfg.blockDim = dim3(1024, 1, 1);
    cfg.dynamicSmemBytes = 0;
    cfg.stream = 0;
    cfg.attrs = attr;
    cfg.numAttrs = 1;
    cudaLaunchKernelEx(&cfg, kBC, out);
}